// round 14
// baseline (speedup 1.0000x reference)
#include <cuda_runtime.h>
#include <cuda_bf16.h>

// C=16, E=64, N=256. Fully fused:
//   O[ce,i] = sum_j v[ce,j]*exp(q[ce,i]*k[ce,j]/8) / sum_j exp(...)
//   Y = reshape(O,(4096,64)) @ W^T + b    (GEMM row = 64 tokens of a channel)
//
// Taylor-moment attention (m=0..8), packed f32x2 phase 1; packed k-pair FFMA2
// phase 2. THIS ROUND: half-size blocks, doubled grid -> 2 blocks/SM so two
// independent serial chains overlap on each SM (all prior versions ran a
// single wave of 1 block/SM and were latency-floor-bound).
// 256 blocks x 256 threads: warps 0-3 compute channels 4*bid..4*bid+3,
// warps 4-7 stage W row-major. One 256-thread barrier. Phase 2: all 8 warps;
// warp w covers feature-quads 2w,2w+1; lane&15 = block row (16 rows).

#define NTERMS 9

__device__ __constant__ float c_invfact[NTERMS] = {
    1.0f, 1.0f, 0.5f,
    1.6666667e-1f, 4.1666667e-2f, 8.3333333e-3f,
    1.3888889e-3f, 1.9841270e-4f, 2.4801587e-5f
};

typedef unsigned long long u64;

__device__ __forceinline__ u64 pack2(float lo, float hi) {
    u64 r; asm("mov.b64 %0, {%1, %2};" : "=l"(r) : "f"(lo), "f"(hi)); return r;
}
__device__ __forceinline__ void unpack2(u64 v, float& lo, float& hi) {
    asm("mov.b64 {%0, %1}, %2;" : "=f"(lo), "=f"(hi) : "l"(v));
}
__device__ __forceinline__ u64 ffma2(u64 a, u64 b, u64 c) {
    u64 d; asm("fma.rn.f32x2 %0, %1, %2, %3;" : "=l"(d) : "l"(a), "l"(b), "l"(c));
    return d;
}
__device__ __forceinline__ u64 fmul2(u64 a, u64 b) {
    u64 d; asm("mul.rn.f32x2 %0, %1, %2;" : "=l"(d) : "l"(a), "l"(b));
    return d;
}
__device__ __forceinline__ u64 fadd2(u64 a, u64 b) {
    u64 d; asm("add.rn.f32x2 %0, %1, %2;" : "=l"(d) : "l"(a), "l"(b));
    return d;
}

// ---------------------------------------------------------------------------
// 256 blocks x 256 threads (8 warps) -> 2 blocks/SM.
// ---------------------------------------------------------------------------
__global__ void __launch_bounds__(256, 2)
ca_fused_kernel(const float* __restrict__ q,
                const float* __restrict__ k,
                const float* __restrict__ v,
                const float* __restrict__ W,
                const float* __restrict__ bias,
                float* __restrict__ Y)
{
    __shared__ float Wsh[64 * 64];   // row-major: Wsh[f*64 + kk]  (16 KB)
    __shared__ float Osh[16 * 68];   // 16 block rows of O; stride 68 (4.25 KB)

    const int t    = threadIdx.x;
    const int wid  = t >> 5;         // 0..7
    const int lane = t & 31;

    // phase-2 feature base: warp w covers quads 2w + (lane>>4)
    const int f0 = (2 * wid + (lane >> 4)) * 4;
    const float4 bias4 = *(const float4*)(bias + f0);

    if (wid < 4) {
        // ================= Phase 1: attention for channel ce ==============
        const int ce = blockIdx.x * 4 + wid;
        const float4* kp4 = (const float4*)(k + ce * 256) + lane * 2;
        const float4* vp4 = (const float4*)(v + ce * 256) + lane * 2;
        const float4* qp4 = (const float4*)(q + ce * 256) + lane * 2;
        float4 kA = kp4[0], kB = kp4[1];
        float4 vA = vp4[0], vB = vp4[1];
        float4 qA = qp4[0], qB = qp4[1];

        u64 b2[8], vv2[8], pw2[8];
        {
            float bb[8] = {kA.x, kA.y, kA.z, kA.w, kB.x, kB.y, kB.z, kB.w};
            float vv[8] = {vA.x, vA.y, vA.z, vA.w, vB.x, vB.y, vB.z, vB.w};
#pragma unroll
            for (int u = 0; u < 8; u++) {
                float bu = bb[u] * 0.125f;
                b2[u]  = pack2(bu, bu);
                vv2[u] = pack2(1.0f, vv[u]);
                pw2[u] = pack2(1.0f, 1.0f);
            }
        }

        u64 M[NTERMS];   // packed {S_m, Mv_m} per-lane partials
#pragma unroll
        for (int m = 0; m < NTERMS; m++) {
            u64 acc = 0ull;
#pragma unroll
            for (int u = 0; u < 8; u++) {
                acc    = ffma2(vv2[u], pw2[u], acc);
                pw2[u] = fmul2(pw2[u], b2[u]);
            }
            M[m] = acc;
        }

        // 5-round packed butterfly; fold 1/m! after
#pragma unroll
        for (int off = 16; off; off >>= 1) {
#pragma unroll
            for (int m = 0; m < NTERMS; m++)
                M[m] = fadd2(M[m], __shfl_xor_sync(0xffffffffu, M[m], off));
        }
#pragma unroll
        for (int m = 0; m < NTERMS; m++) {
            float f = c_invfact[m];
            M[m] = fmul2(M[m], pack2(f, f));
        }

        // Horner per query -> O into smem (scalar stores; stride-68 layout)
        {
            float a[8] = {qA.x, qA.y, qA.z, qA.w, qB.x, qB.y, qB.z, qB.w};
            float* od = &Osh[(wid * 4 + (lane >> 3)) * 68 + (lane & 7) * 8];
#pragma unroll
            for (int u = 0; u < 8; u++) {
                u64 a2 = pack2(a[u], a[u]);
                u64 h = M[NTERMS - 1];
#pragma unroll
                for (int m = NTERMS - 2; m >= 0; m--)
                    h = ffma2(h, a2, M[m]);
                float den, num;
                unpack2(h, den, num);
                od[u] = __fdividef(num, den);
            }
        }
    } else {
        // ================= W staging warps (4-7) ==========================
        const int t2 = t - 128;          // 0..127
#pragma unroll
        for (int i = 0; i < 8; i++) {
            int idx = t2 + 128 * i;
            ((float4*)Wsh)[idx] = ((const float4*)W)[idx];
        }
    }

    __syncthreads();

    // ============ Phase 2: projection (all 8 warps, packed k-pairs) =======
    // lane&15 -> block row; feats f0..f0+3 (quad per lane half).
    const int row = lane & 15;
    const float4* orow4 = (const float4*)&Osh[row * 68];    // 17 float4
    const float* wrow = &Wsh[f0 * 64];

    u64 acc0 = pack2(bias4.x, 0.0f);
    u64 acc1 = pack2(bias4.y, 0.0f);
    u64 acc2 = pack2(bias4.z, 0.0f);
    u64 acc3 = pack2(bias4.w, 0.0f);

#pragma unroll
    for (int c = 0; c < 16; c++) {
        float4 o4 = orow4[c];                       // o[4c..4c+3], LDS.128
        u64 op01 = pack2(o4.x, o4.y);               // {o_ev, o_od}
        u64 op23 = pack2(o4.z, o4.w);
        ulonglong2 w0 = *(const ulonglong2*)&wrow[0 * 64 + 4 * c];  // 2-addr bcast
        ulonglong2 w1 = *(const ulonglong2*)&wrow[1 * 64 + 4 * c];
        ulonglong2 w2 = *(const ulonglong2*)&wrow[2 * 64 + 4 * c];
        ulonglong2 w3 = *(const ulonglong2*)&wrow[3 * 64 + 4 * c];
        acc0 = ffma2(op01, w0.x, acc0);
        acc1 = ffma2(op01, w1.x, acc1);
        acc2 = ffma2(op01, w2.x, acc2);
        acc3 = ffma2(op01, w3.x, acc3);
        acc0 = ffma2(op23, w0.y, acc0);
        acc1 = ffma2(op23, w1.y, acc1);
        acc2 = ffma2(op23, w2.y, acc2);
        acc3 = ffma2(op23, w3.y, acc3);
    }

    // horizontal add even+odd partials, write Y[blockRow][f0..f0+3]
    {
        float e0, d0, e1, d1, e2, d2, e3, d3;
        unpack2(acc0, e0, d0);
        unpack2(acc1, e1, d1);
        unpack2(acc2, e2, d2);
        unpack2(acc3, e3, d3);
        float* yp = &Y[(blockIdx.x * 16 + row) * 64 + f0];
        *(float4*)yp = make_float4(e0 + d0, e1 + d1, e2 + d2, e3 + d3);
    }
}

// ---------------------------------------------------------------------------
extern "C" void kernel_launch(void* const* d_in, const int* in_sizes, int n_in,
                              void* d_out, int out_size)
{
    const float* q  = (const float*)d_in[0];
    const float* k  = (const float*)d_in[1];
    const float* v  = (const float*)d_in[2];
    const float* W  = (const float*)d_in[3];
    const float* b  = (const float*)d_in[4];
    float* out = (float*)d_out;

    ca_fused_kernel<<<256, 256>>>(q, k, v, W, b, out);
    (void)in_sizes; (void)n_in; (void)out_size;
}

// round 15
// speedup vs baseline: 1.2620x; 1.2620x over previous
#include <cuda_runtime.h>
#include <cuda_bf16.h>

// C=16, E=64, N=256. Fully fused:
//   O[ce,i] = sum_j v[ce,j]*exp(q[ce,i]*k[ce,j]/8) / sum_j exp(...)
//   Y = reshape(O,(4096,64)) @ W^T + b    (GEMM row = 64 tokens of a channel)
//
// Taylor-moment attention (m=0..8), packed f32x2; warp-specialized W staging;
// packed k-pair FFMA2 projection. THIS ROUND: compact code. All prior
// versions were fully-unrolled straight-line SASS (~24KB) executed once per
// warp in a single wave -> every I$ line cold; suspected fetch-stall floor.
// Loops are kept rolled (#pragma unroll 1 / unroll 2) to shrink code ~4x.

#define NTERMS 9

__device__ __constant__ float c_invfact[NTERMS] = {
    1.0f, 1.0f, 0.5f,
    1.6666667e-1f, 4.1666667e-2f, 8.3333333e-3f,
    1.3888889e-3f, 1.9841270e-4f, 2.4801587e-5f
};

typedef unsigned long long u64;

__device__ __forceinline__ u64 pack2(float lo, float hi) {
    u64 r; asm("mov.b64 %0, {%1, %2};" : "=l"(r) : "f"(lo), "f"(hi)); return r;
}
__device__ __forceinline__ void unpack2(u64 v, float& lo, float& hi) {
    asm("mov.b64 {%0, %1}, %2;" : "=f"(lo), "=f"(hi) : "l"(v));
}
__device__ __forceinline__ u64 ffma2(u64 a, u64 b, u64 c) {
    u64 d; asm("fma.rn.f32x2 %0, %1, %2, %3;" : "=l"(d) : "l"(a), "l"(b), "l"(c));
    return d;
}
__device__ __forceinline__ u64 fmul2(u64 a, u64 b) {
    u64 d; asm("mul.rn.f32x2 %0, %1, %2;" : "=l"(d) : "l"(a), "l"(b));
    return d;
}
__device__ __forceinline__ u64 fadd2(u64 a, u64 b) {
    u64 d; asm("add.rn.f32x2 %0, %1, %2;" : "=l"(d) : "l"(a), "l"(b));
    return d;
}

// ---------------------------------------------------------------------------
// 128 blocks x 512 threads (16 warps).
// Phase 1: warp w<8 -> channel ce = 8*bid + w; warps 8-15 stage W.
// Phase 2: warp w -> features 4w..4w+3, lane -> block row 0..31.
// ---------------------------------------------------------------------------
__global__ void __launch_bounds__(512)
ca_fused_kernel(const float* __restrict__ q,
                const float* __restrict__ k,
                const float* __restrict__ v,
                const float* __restrict__ W,
                const float* __restrict__ bias,
                float* __restrict__ Y)
{
    __shared__ float Wsh[64 * 64];   // row-major: Wsh[f*64 + kk]
    __shared__ float Osh[32 * 68];   // block rows of O; stride 68 (16B-aligned)

    const int t    = threadIdx.x;
    const int wid  = t >> 5;         // 0..15
    const int lane = t & 31;

    const float4 bias4 = *(const float4*)(bias + wid * 4);

    if (wid < 8) {
        // ================= Phase 1: attention for channel ce ==============
        const int ce = blockIdx.x * 8 + wid;
        const float4* kp4 = (const float4*)(k + ce * 256) + lane * 2;
        const float4* vp4 = (const float4*)(v + ce * 256) + lane * 2;
        const float4* qp4 = (const float4*)(q + ce * 256) + lane * 2;
        float4 kA = kp4[0], kB = kp4[1];
        float4 vA = vp4[0], vB = vp4[1];

        u64 b2[8], vv2[8], pw2[8];
        {
            float bb[8] = {kA.x, kA.y, kA.z, kA.w, kB.x, kB.y, kB.z, kB.w};
            float vv[8] = {vA.x, vA.y, vA.z, vA.w, vB.x, vB.y, vB.z, vB.w};
#pragma unroll
            for (int u = 0; u < 8; u++) {
                float bu = bb[u] * 0.125f;
                b2[u]  = pack2(bu, bu);
                vv2[u] = pack2(1.0f, vv[u]);
                pw2[u] = pack2(1.0f, 1.0f);
            }
        }

        // moment loop: register arrays need compile-time indices -> unrolled,
        // but this is the irreducible compute core (144 FFMA2/FMUL2).
        u64 M[NTERMS];
#pragma unroll
        for (int m = 0; m < NTERMS; m++) {
            u64 acc = 0ull;
#pragma unroll
            for (int u = 0; u < 8; u++) {
                acc    = ffma2(vv2[u], pw2[u], acc);
                pw2[u] = fmul2(pw2[u], b2[u]);
            }
            M[m] = acc;
        }

        // butterfly: ROLLED outer loop (dynamic shfl offset) -> ~20 inst
#pragma unroll 1
        for (int off = 16; off; off >>= 1) {
#pragma unroll
            for (int m = 0; m < NTERMS; m++)
                M[m] = fadd2(M[m], __shfl_xor_sync(0xffffffffu, M[m], off));
        }
#pragma unroll
        for (int m = 0; m < NTERMS; m++) {
            float f = c_invfact[m];
            M[m] = fmul2(M[m], pack2(f, f));
        }

        // Horner: ROLLED loop over two query-quads (body = 4 queries)
        float* od = &Osh[(wid * 4 + (lane >> 3)) * 68 + (lane & 7) * 8];
#pragma unroll 1
        for (int h = 0; h < 2; h++) {
            float4 qv = qp4[h];
            float a[4] = {qv.x, qv.y, qv.z, qv.w};
#pragma unroll
            for (int u = 0; u < 4; u++) {
                u64 a2 = pack2(a[u], a[u]);
                u64 hh = M[NTERMS - 1];
#pragma unroll
                for (int m = NTERMS - 2; m >= 0; m--)
                    hh = ffma2(hh, a2, M[m]);
                float den, num;
                unpack2(hh, den, num);
                od[4 * h + u] = __fdividef(num, den);
            }
        }
    } else {
        // ================= W staging warps (8-15), rolled =================
        const int t2 = t - 256;          // 0..255
#pragma unroll 1
        for (int i = 0; i < 4; i++) {
            int idx = t2 + 256 * i;
            ((float4*)Wsh)[idx] = ((const float4*)W)[idx];
        }
    }

    __syncthreads();

    // ============ Phase 2: projection (all 16 warps, packed k-pairs) ======
    // ROLLED with unroll 2 -> ~35 inst instead of ~210.
    const int f0 = wid * 4;
    const float4* orow4 = (const float4*)&Osh[lane * 68];   // 17 float4
    const float* wrow = &Wsh[f0 * 64];

    u64 acc0 = pack2(bias4.x, 0.0f);
    u64 acc1 = pack2(bias4.y, 0.0f);
    u64 acc2 = pack2(bias4.z, 0.0f);
    u64 acc3 = pack2(bias4.w, 0.0f);

#pragma unroll 2
    for (int c = 0; c < 16; c++) {
        float4 o4 = orow4[c];                       // LDS.128
        u64 op01 = pack2(o4.x, o4.y);
        u64 op23 = pack2(o4.z, o4.w);
        ulonglong2 w0 = *(const ulonglong2*)&wrow[0 * 64 + 4 * c];  // broadcast
        ulonglong2 w1 = *(const ulonglong2*)&wrow[1 * 64 + 4 * c];
        ulonglong2 w2 = *(const ulonglong2*)&wrow[2 * 64 + 4 * c];
        ulonglong2 w3 = *(const ulonglong2*)&wrow[3 * 64 + 4 * c];
        acc0 = ffma2(op01, w0.x, acc0);
        acc1 = ffma2(op01, w1.x, acc1);
        acc2 = ffma2(op01, w2.x, acc2);
        acc3 = ffma2(op01, w3.x, acc3);
        acc0 = ffma2(op23, w0.y, acc0);
        acc1 = ffma2(op23, w1.y, acc1);
        acc2 = ffma2(op23, w2.y, acc2);
        acc3 = ffma2(op23, w3.y, acc3);
    }

    {
        float e0, d0, e1, d1, e2, d2, e3, d3;
        unpack2(acc0, e0, d0);
        unpack2(acc1, e1, d1);
        unpack2(acc2, e2, d2);
        unpack2(acc3, e3, d3);
        float* yp = &Y[(blockIdx.x * 32 + lane) * 64 + f0];
        *(float4*)yp = make_float4(e0 + d0, e1 + d1, e2 + d2, e3 + d3);
    }
}

// ---------------------------------------------------------------------------
extern "C" void kernel_launch(void* const* d_in, const int* in_sizes, int n_in,
                              void* d_out, int out_size)
{
    const float* q  = (const float*)d_in[0];
    const float* k  = (const float*)d_in[1];
    const float* v  = (const float*)d_in[2];
    const float* W  = (const float*)d_in[3];
    const float* b  = (const float*)d_in[4];
    float* out = (float*)d_out;

    ca_fused_kernel<<<128, 512>>>(q, k, v, W, b, out);
    (void)in_sizes; (void)n_in; (void)out_size;
}